// round 1
// baseline (speedup 1.0000x reference)
#include <cuda_runtime.h>

#define SIDE     32
#define UNITS    1024
#define BATCH    128
#define TSTEPS   512
#define NTHREADS 128   // 8 row-groups (4 rows each) x 16 column-pairs

typedef unsigned long long ull;

// Packed fp32x2 FMA (Blackwell FFMA2 — only reachable via PTX, see SASS_QUICKREF)
#define FMA2(acc, a, m) asm("fma.rn.f32x2 %0, %1, %2, %0;" : "+l"(acc) : "l"(a), "l"(m))
#define PACK2(d, lo, hi) asm("mov.b64 %0, {%1, %2};" : "=l"(d) : "f"(lo), "f"(hi))
#define UNPACK2(lo, hi, s) asm("mov.b64 {%0, %1}, %2;" : "=f"(lo), "=f"(hi) : "l"(s))

// A^T store: for this thread's two columns c0,c0+1 write A[r0+r][c] = h + b2,
// duplicated ({v,v}) so the j-loop can load {a,a} pairs directly with LDS.128.
// Layout: Ash[g][j][12]: floats [0..7] = {a0,a0,a1,a1,a2,a2,a3,a3}, [8..11] pad.
__device__ __forceinline__ void store_A(float* dst, int c0, const ull acc[4],
                                        const float* b2c0, const float* b2c1)
{
    float lo[4], hi[4];
#pragma unroll
    for (int r = 0; r < 4; r++) UNPACK2(lo[r], hi[r], acc[r]);
    float a0 = lo[0] + b2c0[0], a1 = lo[1] + b2c0[1];
    float a2 = lo[2] + b2c0[2], a3 = lo[3] + b2c0[3];
    float d0 = hi[0] + b2c1[0], d1 = hi[1] + b2c1[1];
    float d2 = hi[2] + b2c1[2], d3 = hi[3] + b2c1[3];
    float4* p0 = (float4*)(dst + c0 * 12);
    float4* p1 = (float4*)(dst + (c0 + 1) * 12);
    p0[0] = make_float4(a0, a0, a1, a1);
    p0[1] = make_float4(a2, a2, a3, a3);
    p1[0] = make_float4(d0, d0, d1, d1);
    p1[1] = make_float4(d2, d2, d3, d3);
}

__device__ __forceinline__ void store_M(float* dst, float4 xa, float4 xb,
                                        float4 bA, float4 bB)
{
    ((float4*)dst)[0] = make_float4(xa.x + bA.x, xa.y + bA.y, xa.z + bA.z, xa.w + bA.w);
    ((float4*)dst)[1] = make_float4(xb.x + bB.x, xb.y + bB.y, xb.z + bB.z, xb.w + bB.w);
}

__global__ __launch_bounds__(NTHREADS, 1)
void minrnn_kernel(const float* __restrict__ x, const float* __restrict__ bias,
                   const float* __restrict__ bias2, const float* __restrict__ h0,
                   float* __restrict__ out)
{
    __shared__ __align__(16) float Msh[2][UNITS];            // M = b + x_t (double buffered)
    __shared__ __align__(16) float Ash[2][8][SIDE][12];      // A^T dup layout (double buffered)

    const int tid = threadIdx.x;
    const int bb  = blockIdx.x;
    const int k2  = tid & 15;          // column-pair index (cols 2k2, 2k2+1)
    const int g   = tid >> 4;          // row group (rows 4g..4g+3)
    const int c0  = k2 * 2;
    const int r0  = g * 4;

    // bias for M fill: this thread fills units tid*8 .. tid*8+7 each step
    const float4 bA = *(const float4*)(bias + tid * 8);
    const float4 bB = *(const float4*)(bias + tid * 8 + 4);

    // b2 constants for this thread's (4 rows x 2 cols) tile
    float b2c0[4], b2c1[4];
#pragma unroll
    for (int r = 0; r < 4; r++) {
        b2c0[r] = bias2[(r0 + r) * SIDE + c0];
        b2c1[r] = bias2[(r0 + r) * SIDE + c0 + 1];
    }

    // h accumulators: acc[r] = {h[r0+r][c0], h[r0+r][c0+1]} packed f32x2
    ull acc[4];
#pragma unroll
    for (int r = 0; r < 4; r++) {
        const float* hp = h0 + bb * UNITS + (r0 + r) * SIDE + c0;
        PACK2(acc[r], hp[0], hp[1]);
    }

    const float* xp = x + (size_t)bb * TSTEPS * UNITS + tid * 8;

    // x prefetch pipeline, depth 4 (LDG->consume gap ~3 steps > DRAM latency)
    float4 xr0[4], xr1[4];
#pragma unroll
    for (int s = 0; s < 4; s++) {
        xr0[s] = *(const float4*)(xp + s * UNITS);
        xr1[s] = *(const float4*)(xp + s * UNITS + 4);
    }

    // Pre-loop: A^T[0] = h0 + b2, M[0] = b + x(0)
    store_A(&Ash[0][g][0][0], c0, acc, b2c0, b2c1);
    store_M(&Msh[0][tid * 8], xr0[0], xr1[0], bA, bB);
    __syncthreads();

#pragma unroll 4
    for (int t = 0; t < TSTEPS; t++) {
        const int pb = t & 1;

        // refill freed slot with x(t+4)
        if (t + 4 < TSTEPS) {
            xr0[t & 3] = *(const float4*)(xp + (t + 4) * UNITS);
            xr1[t & 3] = *(const float4*)(xp + (t + 4) * UNITS + 4);
        }

        // out[r0+r][c0..c0+1] = sum_j A[r0+r][j] * M[j][c0..c0+1]
        ull n0 = 0, n1 = 0, n2 = 0, n3 = 0;
        const float* Ab = &Ash[pb][g][0][0];
        const float* Mb = &Msh[pb][0];
#pragma unroll
        for (int j = 0; j < SIDE; j++) {
            ulonglong2 a01 = *(const ulonglong2*)(Ab + j * 12);       // {a0,a0},{a1,a1}
            ulonglong2 a23 = *(const ulonglong2*)(Ab + j * 12 + 4);   // {a2,a2},{a3,a3}
            ull mm = *(const ull*)(Mb + j * SIDE + c0);               // {m[j][c0], m[j][c0+1]}
            FMA2(n0, a01.x, mm);
            FMA2(n1, a01.y, mm);
            FMA2(n2, a23.x, mm);
            FMA2(n3, a23.y, mm);
        }
        acc[0] = n0; acc[1] = n1; acc[2] = n2; acc[3] = n3;

        if (t + 1 < TSTEPS) {
            store_A(&Ash[pb ^ 1][g][0][0], c0, acc, b2c0, b2c1);
            store_M(&Msh[pb ^ 1][tid * 8], xr0[(t + 1) & 3], xr1[(t + 1) & 3], bA, bB);
            __syncthreads();
        }
    }

    // write final h (WITHOUT b2)
    float* op = out + bb * UNITS + r0 * SIDE + c0;
#pragma unroll
    for (int r = 0; r < 4; r++) {
        float lo, hi;
        UNPACK2(lo, hi, acc[r]);
        *(float2*)(op + r * SIDE) = make_float2(lo, hi);
    }
}

extern "C" void kernel_launch(void* const* d_in, const int* in_sizes, int n_in,
                              void* d_out, int out_size)
{
    const float* x  = (const float*)d_in[0];   // [128, 512, 1024]
    const float* b  = (const float*)d_in[1];   // [1024]
    const float* b2 = (const float*)d_in[2];   // [1024]
    const float* h0 = (const float*)d_in[3];   // [128, 1024]
    float* out = (float*)d_out;                // [128, 1024]
    minrnn_kernel<<<BATCH, NTHREADS>>>(x, b, b2, h0, out);
}